// round 16
// baseline (speedup 1.0000x reference)
#include <cuda_runtime.h>
#include <cuda_fp16.h>
#include <cstdint>

// SDPA B=4,H=16,S=2048,D=64 fp32. scores = QK^T * 4096 -> one-hot softmax.
// R16: fp8 e4m3 approx pass retry. R15 analysis: legacy-HMMA issue rate is
// the wall (4 warps x 32 MMA x rt~16 ~= the whole tile period), so halving
// MMA count via m16n8k32 e4m3 attacks the binding resource. R14's failure
// re-diagnosed as RING EVICTION (argmax overwritten by later in-window
// pushes), not precision. Fixes: NCAND=64 ring + per-query atomicMax of the
// packed approx score (bmax, never lost) + W=3.5/PF=3.6 (>=6 sigma) + es
// array removed (pass-3 recomputes exact dots on L1-hot K rows).

#define S_LEN 2048
#define HDIM  64
#define TQ    256
#define THREADS 256
#define TKT   64
#define NKT   (S_LEN / TKT)
#define N_BH  64
#define WINAPPROX 3.5f
#define PREFILTER 3.6f
#define WCUT 0.0051f
#define LSCALE 4096.0f
#define NCAND 64
#define KEYMASK 0x7FFu
#define SCOREMASK 0xFFFFF800u

#define TILE_WORDS 1024                   // 4 KB e4m3 tile

#define W_CK  0                                  // u32 packed cand [256][64] = 64 KB
#define W_BM  (W_CK + TQ * NCAND)                // u32 bmax[256]
#define W_CNT (W_BM + TQ)                        // int cnt[256]
#define SMEM_WORDS (W_CNT + TQ)
#define SMEM_BYTES (SMEM_WORDS * 4)              // ~67.6 KB -> 2 CTAs/SM

typedef unsigned long long u64;

__device__ static uint32_t g_kscr[(size_t)N_BH * NKT * TILE_WORDS];  // 8 MB

__device__ __forceinline__ void mma_e4m3(float& d0, float& d1, float& d2, float& d3,
                                         uint32_t a0, uint32_t a1, uint32_t a2, uint32_t a3,
                                         uint32_t b0, uint32_t b1) {
    asm volatile(
        "mma.sync.aligned.m16n8k32.row.col.f32.e4m3.e4m3.f32 "
        "{%0,%1,%2,%3}, {%4,%5,%6,%7}, {%8,%9}, {%0,%1,%2,%3};"
        : "+f"(d0), "+f"(d1), "+f"(d2), "+f"(d3)
        : "r"(a0), "r"(a1), "r"(a2), "r"(a3), "r"(b0), "r"(b1));
}
__device__ __forceinline__ uint32_t e4m3x4(float x0, float x1, float x2, float x3) {
    uint16_t lo, hi;
    asm("cvt.rn.satfinite.e4m3x2.f32 %0, %1, %2;" : "=h"(lo) : "f"(x1), "f"(x0));
    asm("cvt.rn.satfinite.e4m3x2.f32 %0, %1, %2;" : "=h"(hi) : "f"(x3), "f"(x2));
    return (uint32_t)lo | ((uint32_t)hi << 16);
}
__device__ __forceinline__ u64 ffma2(u64 a, u64 b, u64 c) {
    u64 d;
    asm("fma.rn.f32x2 %0, %1, %2, %3;" : "=l"(d) : "l"(a), "l"(b), "l"(c));
    return d;
}
__device__ __forceinline__ u64 fadd2(u64 a, u64 b) {
    u64 d;
    asm("add.rn.f32x2 %0, %1, %2;" : "=l"(d) : "l"(a), "l"(b));
    return d;
}
__device__ __forceinline__ float hsum2(u64 a) {
    float x, y;
    asm("mov.b64 {%0, %1}, %2;" : "=f"(x), "=f"(y) : "l"(a));
    return x + y;
}
__device__ __forceinline__ u64 pack2(float x, float y) {
    u64 d;
    asm("mov.b64 %0, {%1, %2};" : "=l"(d) : "f"(x), "f"(y));
    return d;
}

// ---- pre-pass: K f32 -> fragment-ready e4m3 tiles (layout validated R14) ----
__global__ void __launch_bounds__(256)
k_convert_kernel(const float* __restrict__ K) {
    const int x = blockIdx.x;
    const int tid = threadIdx.x;
    const int bh = x / NKT, kt = x - bh * NKT;
    const float* kt_base = K + ((long)bh * S_LEN + (long)kt * TKT) * HDIM;
    uint32_t* dst = g_kscr + (size_t)x * TILE_WORDS;
#pragma unroll
    for (int i = 0; i < TILE_WORDS / 256; i++) {
        const int w = i * 256 + tid;
        const int ng = w >> 7, iw = w & 127;
        const int l = iw >> 2, r = iw & 3;
        const int ks = r >> 1, b = r & 1;
        const int g = l >> 2, t = l & 3;
        const int key = ng * 8 + g;
        const int dim = 32 * ks + 16 * b + 4 * t;
        const float4 v = *(const float4*)(kt_base + key * HDIM + dim);
        dst[w] = e4m3x4(v.x, v.y, v.z, v.w);
    }
}

__global__ void __launch_bounds__(THREADS, 2)
sdpa_r16_kernel(const float* __restrict__ Q,
                const float* __restrict__ K,
                const float* __restrict__ V,
                float* __restrict__ O) {
    extern __shared__ float sm[];
    uint32_t* ckq  = (uint32_t*)(sm + W_CK);
    uint32_t* bmaxq = (uint32_t*)(sm + W_BM);
    int* cntq = (int*)(sm + W_CNT);

    const int tid  = threadIdx.x;
    const int lane = tid & 31;
    const int warp = tid >> 5;
    const int g    = lane >> 2;
    const int t    = lane & 3;
    const int bh   = blockIdx.y;
    const long bhoff = (long)bh * S_LEN * HDIM;
    const float* kb = K + bhoff;
    const float* vb = V + bhoff;
    const uint4* gfrag = (const uint4*)(g_kscr + (size_t)bh * NKT * TILE_WORDS) + lane;

    cntq[tid] = 0;
    bmaxq[tid] = 0;

    // ---- A fragments (e4m3): warp's 32 query rows, af[mtile][ks][4] ----
    uint32_t af[2][2][4];
    {
        const float* r0 = Q + ((long)bh * S_LEN + blockIdx.x * TQ + warp * 32 + g) * HDIM;
#pragma unroll
        for (int mt = 0; mt < 2; mt++) {
            const float* lo = r0 + mt * 16 * HDIM;
            const float* hi = lo + 8 * HDIM;
#pragma unroll
            for (int ks = 0; ks < 2; ks++) {
                const int base = 32 * ks + 4 * t;
                float4 v;
                v = *(const float4*)(lo + base);      af[mt][ks][0] = e4m3x4(v.x, v.y, v.z, v.w);
                v = *(const float4*)(hi + base);      af[mt][ks][1] = e4m3x4(v.x, v.y, v.z, v.w);
                v = *(const float4*)(lo + base + 16); af[mt][ks][2] = e4m3x4(v.x, v.y, v.z, v.w);
                v = *(const float4*)(hi + base + 16); af[mt][ks][3] = e4m3x4(v.x, v.y, v.z, v.w);
            }
        }
    }

    float mq[4]  = {-INFINITY, -INFINITY, -INFINITY, -INFINITY};
    float thq[4] = {-INFINITY, -INFINITY, -INFINITY, -INFINITY};

    // ---- barrier-free main loop (16 fp8 MMAs + 4 LDG.128 per warp-tile) ----
#pragma unroll 1
    for (int kt = 0; kt < NKT; kt++) {
        const uint4* tf = gfrag + (size_t)kt * (TILE_WORDS / 4);

        float acc[8][8];
#pragma unroll
        for (int nt = 0; nt < 8; nt++)
#pragma unroll
            for (int e = 0; e < 8; e++) acc[nt][e] = 0.0f;

#pragma unroll
        for (int half = 0; half < 2; half++) {
            uint4 bf[4];
#pragma unroll
            for (int i = 0; i < 4; i++)
                bf[i] = __ldg(tf + ((half * 4 + i) << 5));
#pragma unroll
            for (int i = 0; i < 4; i++) {
                const int nt = half * 4 + i;
                mma_e4m3(acc[nt][0], acc[nt][1], acc[nt][2], acc[nt][3],
                         af[0][0][0], af[0][0][1], af[0][0][2], af[0][0][3],
                         bf[i].x, bf[i].y);
                mma_e4m3(acc[nt][4], acc[nt][5], acc[nt][6], acc[nt][7],
                         af[1][0][0], af[1][0][1], af[1][0][2], af[1][0][3],
                         bf[i].x, bf[i].y);
            }
#pragma unroll
            for (int i = 0; i < 4; i++) {
                const int nt = half * 4 + i;
                mma_e4m3(acc[nt][0], acc[nt][1], acc[nt][2], acc[nt][3],
                         af[0][1][0], af[0][1][1], af[0][1][2], af[0][1][3],
                         bf[i].z, bf[i].w);
                mma_e4m3(acc[nt][4], acc[nt][5], acc[nt][6], acc[nt][7],
                         af[1][1][0], af[1][1][1], af[1][1][2], af[1][1][3],
                         bf[i].z, bf[i].w);
            }
        }

        const int kbase = kt * TKT;
#pragma unroll
        for (int qi = 0; qi < 4; qi++) {
            float mx = fmaxf(acc[0][2 * qi], acc[0][2 * qi + 1]);
#pragma unroll
            for (int nt = 1; nt < 8; nt++)
                mx = fmaxf(mx, fmaxf(acc[nt][2 * qi], acc[nt][2 * qi + 1]));
            mx = fmaxf(mx, __shfl_xor_sync(0xFFFFFFFFu, mx, 1));
            mx = fmaxf(mx, __shfl_xor_sync(0xFFFFFFFFu, mx, 2));

            if (mx > thq[qi]) {
                mq[qi] = fmaxf(mq[qi], mx);
                thq[qi] = mq[qi] - WINAPPROX;
                const int q = warp * 32 + g + 8 * qi;
#pragma unroll
                for (int nt = 0; nt < 8; nt++) {
#pragma unroll
                    for (int e = 0; e < 2; e++) {
                        const float s = acc[nt][2 * qi + e];
                        if (s > thq[qi]) {
                            const uint32_t key = (uint32_t)(kbase + nt * 8 + 2 * t + e);
                            const uint32_t pw = (__float_as_uint(s) & SCOREMASK) | key;
                            const int slot = atomicAdd(&cntq[q], 1) & (NCAND - 1);
                            ckq[q * NCAND + slot] = pw;
                            atomicMax(&bmaxq[q], pw & SCOREMASK);  // never lost
                        }
                    }
                }
            }
        }
    }

    __syncthreads();   // all candidate pushes visible

    // ---- epilogue: bmax-anchored prefilter, exact rescore, sparse V ----
    {
        const long qrow = (long)bh * S_LEN + blockIdx.x * TQ + tid;
        const u64* qg = (const u64*)(Q + qrow * HDIM);
        u64 q2[HDIM / 2];
#pragma unroll
        for (int j = 0; j < HDIM / 2; j++) q2[j] = qg[j];

        int nc = cntq[tid];
        if (nc > NCAND) nc = NCAND;
        const float amax = __uint_as_float(bmaxq[tid]);
        const float pfthr = amax - PREFILTER;

        // pass 2: exact rescore of survivors -> em (no storage)
        float em = -INFINITY;
        for (int i = 0; i < nc; i++) {
            const uint32_t cw = ckq[tid * NCAND + i];
            if (__uint_as_float(cw & SCOREMASK) > pfthr) {
                const u64* kr = (const u64*)(kb + (long)(cw & KEYMASK) * HDIM);
                u64 a0 = 0ULL, a1 = 0ULL, a2 = 0ULL, a3 = 0ULL;
#pragma unroll
                for (int j = 0; j < 8; j++) {
                    a0 = ffma2(q2[4 * j + 0], kr[4 * j + 0], a0);
                    a1 = ffma2(q2[4 * j + 1], kr[4 * j + 1], a1);
                    a2 = ffma2(q2[4 * j + 2], kr[4 * j + 2], a2);
                    a3 = ffma2(q2[4 * j + 3], kr[4 * j + 3], a3);
                }
                em = fmaxf(em, hsum2(fadd2(fadd2(a0, a1), fadd2(a2, a3))));
            }
        }

        // pass 3: recompute exact (K rows L1-hot), weight, gather V
        u64 o2[HDIM / 2];
#pragma unroll
        for (int j = 0; j < HDIM / 2; j++) o2[j] = 0ULL;
        float lsum = 0.0f;
        const float wthr = em - WCUT;
        for (int i = 0; i < nc; i++) {
            const uint32_t cw = ckq[tid * NCAND + i];
            if (__uint_as_float(cw & SCOREMASK) > pfthr) {
                const u64* kr = (const u64*)(kb + (long)(cw & KEYMASK) * HDIM);
                u64 a0 = 0ULL, a1 = 0ULL, a2 = 0ULL, a3 = 0ULL;
#pragma unroll
                for (int j = 0; j < 8; j++) {
                    a0 = ffma2(q2[4 * j + 0], kr[4 * j + 0], a0);
                    a1 = ffma2(q2[4 * j + 1], kr[4 * j + 1], a1);
                    a2 = ffma2(q2[4 * j + 2], kr[4 * j + 2], a2);
                    a3 = ffma2(q2[4 * j + 3], kr[4 * j + 3], a3);
                }
                const float e = hsum2(fadd2(fadd2(a0, a1), fadd2(a2, a3)));
                if (e > wthr) {
                    const float w = __expf(LSCALE * (e - em));
                    lsum += w;
                    const u64* v2 = (const u64*)(vb + (long)(cw & KEYMASK) * HDIM);
                    const u64 w2 = pack2(w, w);
#pragma unroll
                    for (int j = 0; j < HDIM / 2; j++) o2[j] = ffma2(w2, v2[j], o2[j]);
                }
            }
        }
        const float inv = 1.0f / lsum;
        const u64 inv2 = pack2(inv, inv);
        u64* og = (u64*)(O + qrow * HDIM);
#pragma unroll
        for (int j = 0; j < HDIM / 2; j++) {
            u64 r;
            asm("mul.rn.f32x2 %0, %1, %2;" : "=l"(r) : "l"(o2[j]), "l"(inv2));
            og[j] = r;
        }
    }
}

extern "C" void kernel_launch(void* const* d_in, const int* in_sizes, int n_in,
                              void* d_out, int out_size) {
    const float* Q = (const float*)d_in[0];
    const float* K = (const float*)d_in[1];
    const float* V = (const float*)d_in[2];
    float* O = (float*)d_out;

    k_convert_kernel<<<N_BH * NKT, 256>>>(K);

    cudaFuncSetAttribute(sdpa_r16_kernel,
                         cudaFuncAttributeMaxDynamicSharedMemorySize, SMEM_BYTES);
    dim3 grid(S_LEN / TQ, N_BH);  // (8, 64)
    dim3 block(THREADS);
    sdpa_r16_kernel<<<grid, block, SMEM_BYTES>>>(Q, K, V, O);
}

// round 17
// speedup vs baseline: 2.4254x; 2.4254x over previous
#include <cuda_runtime.h>
#include <cuda_fp16.h>
#include <cstdint>

// SDPA B=4,H=16,S=2048,D=64 fp32. scores = QK^T * 4096 -> one-hot softmax.
// R17: R13 (217us champion: barrier-free fp16 mma, direct LDG of
// pre-converted fragments, packed-candidate prefilter) with non-MMA issue
// trimming: (1) zero-C first MMA kills the 64-reg acc zero-init per tile,
// (2) balanced fmax tree in the scan, (3) running tile pointer.
// fp8 is dead: R16 showed e4m3 k32 runs at the SAME MACs/cyc as f16 k16 on
// the legacy mma.sync path, and the wide window made the scan hot.

#define S_LEN 2048
#define HDIM  64
#define TQ    256
#define THREADS 256
#define TKT   64
#define NKT   (S_LEN / TKT)
#define N_BH  64
#define WINAPPROX 0.12f
#define PREFILTER 0.05f
#define WCUT 0.0051f
#define LSCALE 4096.0f
#define NCAND 32
#define KEYMASK 0x7FFu
#define SCOREMASK 0xFFFFF800u

#define TILE_WORDS 2048

#define W_CK  0                                  // u32 packed cand [256][32]
#define W_ES  (W_CK + TQ * NCAND)                // float es[32][256]
#define W_CNT (W_ES + TQ * NCAND)                // int cnt[256]
#define SMEM_WORDS (W_CNT + TQ)
#define SMEM_BYTES (SMEM_WORDS * 4)              // ~66.6 KB -> 2 CTAs/SM

typedef unsigned long long u64;

__device__ static uint32_t g_kscr[(size_t)N_BH * NKT * TILE_WORDS];

__device__ __forceinline__ void mma_f16(float& d0, float& d1, float& d2, float& d3,
                                        uint32_t a0, uint32_t a1, uint32_t a2, uint32_t a3,
                                        uint32_t b0, uint32_t b1) {
    asm volatile(
        "mma.sync.aligned.m16n8k16.row.col.f32.f16.f16.f32 "
        "{%0,%1,%2,%3}, {%4,%5,%6,%7}, {%8,%9}, {%0,%1,%2,%3};"
        : "+f"(d0), "+f"(d1), "+f"(d2), "+f"(d3)
        : "r"(a0), "r"(a1), "r"(a2), "r"(a3), "r"(b0), "r"(b1));
}
// first-touch MMA: C = 0 (ptxas materializes RZ), writes acc directly --
// removes the per-tile 64-register accumulator zero-init.
__device__ __forceinline__ void mma_f16_zc(float& d0, float& d1, float& d2, float& d3,
                                           uint32_t a0, uint32_t a1, uint32_t a2, uint32_t a3,
                                           uint32_t b0, uint32_t b1) {
    asm volatile(
        "mma.sync.aligned.m16n8k16.row.col.f32.f16.f16.f32 "
        "{%0,%1,%2,%3}, {%4,%5,%6,%7}, {%8,%9}, {%10,%11,%12,%13};"
        : "=f"(d0), "=f"(d1), "=f"(d2), "=f"(d3)
        : "r"(a0), "r"(a1), "r"(a2), "r"(a3), "r"(b0), "r"(b1),
          "f"(0.0f), "f"(0.0f), "f"(0.0f), "f"(0.0f));
}
__device__ __forceinline__ uint32_t f16x2(float lo, float hi) {
    uint32_t d;
    asm("cvt.rn.f16x2.f32 %0, %1, %2;" : "=r"(d) : "f"(hi), "f"(lo));
    return d;
}
__device__ __forceinline__ u64 ffma2(u64 a, u64 b, u64 c) {
    u64 d;
    asm("fma.rn.f32x2 %0, %1, %2, %3;" : "=l"(d) : "l"(a), "l"(b), "l"(c));
    return d;
}
__device__ __forceinline__ u64 fadd2(u64 a, u64 b) {
    u64 d;
    asm("add.rn.f32x2 %0, %1, %2;" : "=l"(d) : "l"(a), "l"(b));
    return d;
}
__device__ __forceinline__ float hsum2(u64 a) {
    float x, y;
    asm("mov.b64 {%0, %1}, %2;" : "=f"(x), "=f"(y) : "l"(a));
    return x + y;
}
__device__ __forceinline__ u64 pack2(float x, float y) {
    u64 d;
    asm("mov.b64 %0, {%1, %2};" : "=l"(d) : "f"(x), "f"(y));
    return d;
}

__global__ void __launch_bounds__(256)
k_convert_kernel(const float* __restrict__ K) {
    const int x = blockIdx.x;
    const int tid = threadIdx.x;
    const int bh = x / NKT, kt = x - bh * NKT;
    const float* kt_base = K + ((long)bh * S_LEN + (long)kt * TKT) * HDIM;
    uint32_t* dst = g_kscr + (size_t)x * TILE_WORDS;
#pragma unroll
    for (int i = 0; i < TILE_WORDS / 256; i++) {
        const int w = i * 256 + tid;
        const int b = w >> 7, iw = w & 127;
        const int nt = b >> 1, p = b & 1;
        const int n = nt * 8 + (iw >> 4);
        const int c = (iw >> 2) & 3, q = iw & 3;
        const int ks = 2 * p + (q >> 1);
        const int d2 = 8 * ks + 4 * (q & 1) + c;
        const float2 v = *(const float2*)(kt_base + n * HDIM + 2 * d2);
        dst[w] = f16x2(v.x, v.y);
    }
}

__global__ void __launch_bounds__(THREADS, 2)
sdpa_r17_kernel(const float* __restrict__ Q,
                const float* __restrict__ K,
                const float* __restrict__ V,
                float* __restrict__ O) {
    extern __shared__ float sm[];
    uint32_t* ckq = (uint32_t*)(sm + W_CK);
    int* cntq = (int*)(sm + W_CNT);

    const int tid  = threadIdx.x;
    const int lane = tid & 31;
    const int warp = tid >> 5;
    const int g    = lane >> 2;
    const int t    = lane & 3;
    const int bh   = blockIdx.y;
    const long bhoff = (long)bh * S_LEN * HDIM;
    const float* kb = K + bhoff;
    const float* vb = V + bhoff;

    cntq[tid] = 0;

    // ---- A fragments: warp's 32 query rows ----
    uint32_t af[4][8];
    {
        const float* r0 = Q + ((long)bh * S_LEN + blockIdx.x * TQ + warp * 32 + g) * HDIM;
#pragma unroll
        for (int s = 0; s < 4; s++) {
            const int c = 16 * s + 2 * t;
            float2 v;
            v = *(const float2*)(r0 + c);                 af[s][0] = f16x2(v.x, v.y);
            v = *(const float2*)(r0 + 8 * HDIM + c);      af[s][1] = f16x2(v.x, v.y);
            v = *(const float2*)(r0 + c + 8);             af[s][2] = f16x2(v.x, v.y);
            v = *(const float2*)(r0 + 8 * HDIM + c + 8);  af[s][3] = f16x2(v.x, v.y);
            v = *(const float2*)(r0 + 16 * HDIM + c);     af[s][4] = f16x2(v.x, v.y);
            v = *(const float2*)(r0 + 24 * HDIM + c);     af[s][5] = f16x2(v.x, v.y);
            v = *(const float2*)(r0 + 16 * HDIM + c + 8); af[s][6] = f16x2(v.x, v.y);
            v = *(const float2*)(r0 + 24 * HDIM + c + 8); af[s][7] = f16x2(v.x, v.y);
        }
    }

    float mq[4]  = {-INFINITY, -INFINITY, -INFINITY, -INFINITY};
    float thq[4] = {-INFINITY, -INFINITY, -INFINITY, -INFINITY};

    // running tile pointer (no per-iter kt*512 math)
    const uint4* tf = (const uint4*)(g_kscr + (size_t)bh * NKT * TILE_WORDS) + lane;

    // ---- barrier-free main loop ----
#pragma unroll 1
    for (int kt = 0; kt < NKT; kt++, tf += TILE_WORDS / 4) {
        float acc[8][8];   // written by zero-C MMAs (no init)

        // p = 0: ks-step 0 initializes acc via zero-C MMA; ks-step 1 accumulates
#pragma unroll
        for (int ng = 0; ng < 2; ng++) {
            uint4 bf[4];
#pragma unroll
            for (int i = 0; i < 4; i++)
                bf[i] = __ldg(tf + (((ng * 4 + i) * 2) << 5));
#pragma unroll
            for (int i = 0; i < 4; i++) {
                const int nt = ng * 4 + i;
                mma_f16_zc(acc[nt][0], acc[nt][1], acc[nt][2], acc[nt][3],
                           af[0][0], af[0][1], af[0][2], af[0][3],
                           bf[i].x, bf[i].y);
                mma_f16_zc(acc[nt][4], acc[nt][5], acc[nt][6], acc[nt][7],
                           af[0][4], af[0][5], af[0][6], af[0][7],
                           bf[i].x, bf[i].y);
            }
#pragma unroll
            for (int i = 0; i < 4; i++) {
                const int nt = ng * 4 + i;
                mma_f16(acc[nt][0], acc[nt][1], acc[nt][2], acc[nt][3],
                        af[1][0], af[1][1], af[1][2], af[1][3],
                        bf[i].z, bf[i].w);
                mma_f16(acc[nt][4], acc[nt][5], acc[nt][6], acc[nt][7],
                        af[1][4], af[1][5], af[1][6], af[1][7],
                        bf[i].z, bf[i].w);
            }
        }
        // p = 1: both ks-steps accumulate
#pragma unroll
        for (int ng = 0; ng < 2; ng++) {
            uint4 bf[4];
#pragma unroll
            for (int i = 0; i < 4; i++)
                bf[i] = __ldg(tf + (((ng * 4 + i) * 2 + 1) << 5));
#pragma unroll
            for (int i = 0; i < 4; i++) {
                const int nt = ng * 4 + i;
                mma_f16(acc[nt][0], acc[nt][1], acc[nt][2], acc[nt][3],
                        af[2][0], af[2][1], af[2][2], af[2][3],
                        bf[i].x, bf[i].y);
                mma_f16(acc[nt][4], acc[nt][5], acc[nt][6], acc[nt][7],
                        af[2][4], af[2][5], af[2][6], af[2][7],
                        bf[i].x, bf[i].y);
            }
#pragma unroll
            for (int i = 0; i < 4; i++) {
                const int nt = ng * 4 + i;
                mma_f16(acc[nt][0], acc[nt][1], acc[nt][2], acc[nt][3],
                        af[3][0], af[3][1], af[3][2], af[3][3],
                        bf[i].z, bf[i].w);
                mma_f16(acc[nt][4], acc[nt][5], acc[nt][6], acc[nt][7],
                        af[3][4], af[3][5], af[3][6], af[3][7],
                        bf[i].z, bf[i].w);
            }
        }

        // ---- in-register scan, balanced fmax tree ----
        const int kbase = kt * TKT;
#pragma unroll
        for (int qi = 0; qi < 4; qi++) {
            float pr[8];
#pragma unroll
            for (int nt = 0; nt < 8; nt++)
                pr[nt] = fmaxf(acc[nt][2 * qi], acc[nt][2 * qi + 1]);
            float mx = fmaxf(fmaxf(fmaxf(pr[0], pr[1]), fmaxf(pr[2], pr[3])),
                             fmaxf(fmaxf(pr[4], pr[5]), fmaxf(pr[6], pr[7])));
            mx = fmaxf(mx, __shfl_xor_sync(0xFFFFFFFFu, mx, 1));
            mx = fmaxf(mx, __shfl_xor_sync(0xFFFFFFFFu, mx, 2));

            if (mx > thq[qi]) {   // rare
                mq[qi] = fmaxf(mq[qi], mx);
                thq[qi] = mq[qi] - WINAPPROX;
                const int q = warp * 32 + g + 8 * qi;
#pragma unroll
                for (int nt = 0; nt < 8; nt++) {
#pragma unroll
                    for (int e = 0; e < 2; e++) {
                        const float s = acc[nt][2 * qi + e];
                        if (s > thq[qi]) {
                            const int slot = atomicAdd(&cntq[q], 1);
                            if (slot < NCAND) {
                                const uint32_t key = (uint32_t)(kbase + nt * 8 + 2 * t + e);
                                ckq[q * NCAND + slot] =
                                    (__float_as_uint(s) & SCOREMASK) | key;
                            }
                        }
                    }
                }
            }
        }
    }

    __syncthreads();   // all warps' candidate pushes visible

    // ---- epilogue: packed-prefiltered exact rescore + sparse V gather ----
    {
        float* es = sm + W_ES;   // [i*TQ + tid]

        const long qrow = (long)bh * S_LEN + blockIdx.x * TQ + tid;
        const u64* qg = (const u64*)(Q + qrow * HDIM);
        u64 q2[HDIM / 2];
#pragma unroll
        for (int j = 0; j < HDIM / 2; j++) q2[j] = qg[j];

        int nc = cntq[tid];
        if (nc > NCAND) nc = NCAND;

        // pass 1: approx max over packed candidate scores
        float amax = -INFINITY;
        for (int i = 0; i < nc; i++)
            amax = fmaxf(amax, __uint_as_float(ckq[tid * NCAND + i] & SCOREMASK));
        const float pfthr = amax - PREFILTER;

        // pass 2: exact rescore of survivors only (typically 1-3)
        float em = -INFINITY;
        for (int i = 0; i < nc; i++) {
            const uint32_t cw = ckq[tid * NCAND + i];
            float e = -INFINITY;
            if (__uint_as_float(cw & SCOREMASK) > pfthr) {
                const u64* kr = (const u64*)(kb + (long)(cw & KEYMASK) * HDIM);
                u64 a0 = 0ULL, a1 = 0ULL, a2 = 0ULL, a3 = 0ULL;
#pragma unroll
                for (int j = 0; j < 8; j++) {
                    a0 = ffma2(q2[4 * j + 0], kr[4 * j + 0], a0);
                    a1 = ffma2(q2[4 * j + 1], kr[4 * j + 1], a1);
                    a2 = ffma2(q2[4 * j + 2], kr[4 * j + 2], a2);
                    a3 = ffma2(q2[4 * j + 3], kr[4 * j + 3], a3);
                }
                e = hsum2(fadd2(fadd2(a0, a1), fadd2(a2, a3)));
                em = fmaxf(em, e);
            }
            es[i * TQ + tid] = e;
        }

        // pass 3: weights + V gather for exact winners only (typically 1-2)
        u64 o2[HDIM / 2];
#pragma unroll
        for (int j = 0; j < HDIM / 2; j++) o2[j] = 0ULL;
        float lsum = 0.0f;
        const float wthr = em - WCUT;
        for (int i = 0; i < nc; i++) {
            const float e = es[i * TQ + tid];
            if (e > wthr) {
                const float w = __expf(LSCALE * (e - em));
                lsum += w;
                const u64* v2 =
                    (const u64*)(vb + (long)(ckq[tid * NCAND + i] & KEYMASK) * HDIM);
                const u64 w2 = pack2(w, w);
#pragma unroll
                for (int j = 0; j < HDIM / 2; j++) o2[j] = ffma2(w2, v2[j], o2[j]);
            }
        }
        const float inv = 1.0f / lsum;
        const u64 inv2 = pack2(inv, inv);
        u64* og = (u64*)(O + qrow * HDIM);
#pragma unroll
        for (int j = 0; j < HDIM / 2; j++) {
            u64 r;
            asm("mul.rn.f32x2 %0, %1, %2;" : "=l"(r) : "l"(o2[j]), "l"(inv2));
            og[j] = r;
        }
    }
}

extern "C" void kernel_launch(void* const* d_in, const int* in_sizes, int n_in,
                              void* d_out, int out_size) {
    const float* Q = (const float*)d_in[0];
    const float* K = (const float*)d_in[1];
    const float* V = (const float*)d_in[2];
    float* O = (float*)d_out;

    k_convert_kernel<<<N_BH * NKT, 256>>>(K);

    cudaFuncSetAttribute(sdpa_r17_kernel,
                         cudaFuncAttributeMaxDynamicSharedMemorySize, SMEM_BYTES);
    dim3 grid(S_LEN / TQ, N_BH);  // (8, 64)
    dim3 block(THREADS);
    sdpa_r17_kernel<<<grid, block, SMEM_BYTES>>>(Q, K, V, O);
}